// round 15
// baseline (speedup 1.0000x reference)
#include <cuda_runtime.h>
#include <cuda_bf16.h>
#include <stdint.h>
#include <math.h>

typedef __nv_bfloat16 bf16;

#define DIM   512
#define MTOK  512
#define NG    65536
#define ATT_SCALE 0.125f
#define POOL_SHIFT (-100.0f)
#define ZSL   16
#define KSL   (NG / ZSL)            // 4096

// SMEM: K-chunk 32. NT tiles: 128 rows x 64B (XOR swizzle q^((r>>1)&3)).
// Trans-B tiles: 32 k-rows x 256B (XOR swizzle q^(r&7)). Both 8KB.
#define ROWB 64
#define TILEB (128 * ROWB)          // 8192
#define STAGEB (4 * TILEB)          // 32768: Ah | Al | Bh | Bl
#define STAGES 3
#define GEMM_SMEM (STAGES * STAGEB) // 98304  -> 2 CTAs per SM

// ---------------- scratch (device globals; no allocations allowed) ----------
__device__ float d_OP[(size_t)NG * DIM];
__device__ float d_parts[(size_t)ZSL * MTOK * DIM];
__device__ float d_kp[MTOK * DIM];
__device__ float d_Km[MTOK * DIM];
__device__ float d_Vt[DIM * MTOK];
__device__ float d_sums[NG];
__device__ float d_sums1[MTOK];
__device__ float d_biasK[MTOK];
__device__ bf16 d_gh[(size_t)NG * DIM],   d_gl[(size_t)NG * DIM];
__device__ bf16 d_gph[(size_t)NG * DIM],  d_gpl[(size_t)NG * DIM];
__device__ bf16 d_Ph[(size_t)NG * MTOK],  d_Pl[(size_t)NG * MTOK];
__device__ bf16 d_Wsh[MTOK * DIM], d_Wsl[MTOK * DIM];
__device__ bf16 d_B1h[MTOK * DIM], d_B1l[MTOK * DIM];
__device__ bf16 d_B2h[MTOK * DIM], d_B2l[MTOK * DIM];
__device__ bf16 d_Vth[DIM * MTOK], d_Vtl[DIM * MTOK];

// ---------------- helpers ----------------
__device__ __forceinline__ uint32_t smem_u32(const void* p) {
    uint32_t a;
    asm("{ .reg .u64 t; cvta.to.shared.u64 t, %1; cvt.u32.u64 %0, t; }" : "=r"(a) : "l"(p));
    return a;
}
__device__ __forceinline__ void ldsm4(uint32_t* r, uint32_t addr) {
    asm volatile("ldmatrix.sync.aligned.m8n8.x4.shared.b16 {%0,%1,%2,%3}, [%4];"
        : "=r"(r[0]), "=r"(r[1]), "=r"(r[2]), "=r"(r[3]) : "r"(addr));
}
__device__ __forceinline__ void ldsm4t(uint32_t* r, uint32_t addr) {
    asm volatile("ldmatrix.sync.aligned.m8n8.x4.trans.shared.b16 {%0,%1,%2,%3}, [%4];"
        : "=r"(r[0]), "=r"(r[1]), "=r"(r[2]), "=r"(r[3]) : "r"(addr));
}
__device__ __forceinline__ void mma16816(float* c, const uint32_t* a, uint32_t b0, uint32_t b1) {
    asm volatile("mma.sync.aligned.m16n8k16.row.col.f32.bf16.bf16.f32 "
        "{%0,%1,%2,%3}, {%4,%5,%6,%7}, {%8,%9}, {%0,%1,%2,%3};"
        : "+f"(c[0]), "+f"(c[1]), "+f"(c[2]), "+f"(c[3])
        : "r"(a[0]), "r"(a[1]), "r"(a[2]), "r"(a[3]), "r"(b0), "r"(b1));
}
__device__ __forceinline__ void cp16(uint32_t saddr, const void* gaddr) {
    asm volatile("cp.async.cg.shared.global [%0], [%1], 16;" :: "r"(saddr), "l"(gaddr));
}
__device__ __forceinline__ void cp_commit() { asm volatile("cp.async.commit_group;"); }
template<int N> __device__ __forceinline__ void cp_wait() {
    asm volatile("cp.async.wait_group %0;" :: "n"(N) : "memory");
}

// ---------------------------------------------------------------------------
// bf16x3 GEMM via mma.sync. 128x128 tile, 8 warps (32x64 warp tiles),
// K-chunks of 32, XOR-swizzled SMEM (2 CTAs/SM), 3-stage pipeline, single
// sync per chunk, ks-outer fragment reuse.
// NT mode (bTrans=0): C = alpha*(A1·B1^T + A2·B2^T) + biasN, B row-major [n,k].
// NN mode (bTrans=1): B1 is [k, n] with row stride ldbT (single source only).
// Output fp32 and/or bf16 hi/lo pair; doExp: v=exp(v+expShift) before pair
// output; sums gets atomic row sums. swapXY=1: m-tile on blockIdx.x.
// ---------------------------------------------------------------------------
__global__ void __launch_bounds__(256, 2)
gemm3(const bf16* __restrict__ A1h, const bf16* __restrict__ A1l,
      const bf16* __restrict__ B1h, const bf16* __restrict__ B1l, int K1,
      const bf16* __restrict__ A2h, const bf16* __restrict__ A2l,
      const bf16* __restrict__ B2h, const bf16* __restrict__ B2l, int K2,
      float* __restrict__ Cf, int ldc, float alpha,
      const float* __restrict__ biasN,
      bf16* __restrict__ Chi, bf16* __restrict__ Clo, int doExp, float expShift,
      float* __restrict__ sums, int swapXY, int bTrans, int ldbT,
      int kslice, size_t partStride)
{
    extern __shared__ __align__(16) char smem[];
    const uint32_t sb = smem_u32(smem);
    const int tid = threadIdx.x, lane = tid & 31, wid = tid >> 5;
    const int warpM = wid & 3, warpN = wid >> 2;
    const int m0 = (swapXY ? blockIdx.x : blockIdx.y) * 128;
    const int n0 = (swapXY ? blockIdx.y : blockIdx.x) * 128;
    const int k0 = blockIdx.z * kslice;

    const int nk1 = kslice >> 5;
    const int nk2 = A2h ? (K2 >> 5) : 0;
    const int nt = nk1 + nk2;

    float acc[2][8][4];
#pragma unroll
    for (int i = 0; i < 2; ++i)
#pragma unroll
        for (int j = 0; j < 8; ++j)
#pragma unroll
            for (int q = 0; q < 4; ++q) acc[i][j][q] = 0.f;

    auto loadChunk = [&](int c, int s) {
        const bf16 *Ah, *Al, *Bh, *Bl; int K, kb;
        if (c < nk1) { Ah = A1h; Al = A1l; Bh = B1h; Bl = B1l; K = K1; kb = k0 + (c << 5); }
        else         { Ah = A2h; Al = A2l; Bh = B2h; Bl = B2l; K = K2; kb = (c - nk1) << 5; }
        const uint32_t base = sb + s * STAGEB;
        if (!bTrans) {
#pragma unroll
            for (int i = 0; i < 8; ++i) {
                int idx = (i << 8) + tid;            // 0..2047
                int tile = idx >> 9;                 // 0..3
                int rem = idx & 511;
                int row = rem >> 2, q = rem & 3;
                int sw = q ^ ((row >> 1) & 3);
                uint32_t so = base + tile * TILEB + row * ROWB + sw * 16;
                const bf16* src;
                if      (tile == 0) src = Ah + (size_t)(m0 + row) * (size_t)K;
                else if (tile == 1) src = Al + (size_t)(m0 + row) * (size_t)K;
                else if (tile == 2) src = Bh + (size_t)(n0 + row) * (size_t)K;
                else                src = Bl + (size_t)(n0 + row) * (size_t)K;
                cp16(so, src + (size_t)(kb + q * 8));
            }
        } else {
            // A tiles: unchanged (128 rows x 4 units, NT layout)
#pragma unroll
            for (int i = 0; i < 4; ++i) {
                int idx = (i << 8) + tid;            // 0..1023
                int tile = idx >> 9;                 // 0..1
                int rem = idx & 511;
                int row = rem >> 2, q = rem & 3;
                int sw = q ^ ((row >> 1) & 3);
                uint32_t so = base + tile * TILEB + row * ROWB + sw * 16;
                const bf16* src = (tile ? Al : Ah) + (size_t)(m0 + row) * (size_t)K;
                cp16(so, src + (size_t)(kb + q * 8));
            }
            // B tiles: k-major [32 k-rows x 128 n-cols], row = 256B = 16 units,
            // swizzle q^(row&7)
#pragma unroll
            for (int i = 0; i < 4; ++i) {
                int idx = (i << 8) + tid;            // 0..1023
                int tile = idx >> 9;                 // 0..1
                int rem = idx & 511;
                int row = rem >> 4, q = rem & 15;    // 32 rows x 16 units
                int sw = q ^ (row & 7);
                uint32_t so = base + (2 + tile) * TILEB + row * 256 + sw * 16;
                const bf16* src = (tile ? B1l : B1h) + (size_t)(kb + row) * (size_t)ldbT;
                cp16(so, src + (size_t)(n0 + q * 8));
            }
        }
        cp_commit();
    };

    const uint32_t nrow = (((uint32_t)lane >> 4) << 3) + (lane & 7);
    const uint32_t aRowOff = (uint32_t)(warpM * 32 + (lane & 15)) * ROWB;
    const uint32_t bRowOff = (uint32_t)(warpN * 64 + nrow) * ROWB;
    const uint32_t swA = (((uint32_t)lane & 15) >> 1) & 3;
    const uint32_t swB = (nrow >> 1) & 3;
    const uint32_t uA0 = (uint32_t)lane >> 4;          // k-half select for A
    const uint32_t uB0 = ((uint32_t)lane >> 3) & 1;    // k-half select for B
    // trans-B read geometry: row = ks*16 + (lane&15); per nj:
    // u0 = warpN*8 + nj*2 + (lane>>4), sw = u0 ^ (lane&7)  (ks*16 % 8 == 0)
    const uint32_t tRow = (uint32_t)lane & 15;
    const uint32_t tHalf = (uint32_t)lane >> 4;
    const uint32_t tLow = (uint32_t)lane & 7;

    auto compute = [&](int s) {
        const uint32_t base = sb + s * STAGEB;
        const uint32_t sAh = base + aRowOff;
        const uint32_t sAl = sAh + TILEB;
#pragma unroll
        for (int ks = 0; ks < 2; ++ks) {
            const uint32_t offA = (((uint32_t)(ks * 2) + uA0) ^ swA) << 4;
            uint32_t ah[2][4], al[2][4];
#pragma unroll
            for (int mi = 0; mi < 2; ++mi) {
                ldsm4(ah[mi], sAh + mi * 16 * ROWB + offA);
                ldsm4(al[mi], sAl + mi * 16 * ROWB + offA);
            }
            uint32_t bh[4][4], bl[4][4];
            if (!bTrans) {
                const uint32_t sBh = base + 2 * TILEB + bRowOff;
                const uint32_t sBl = sBh + TILEB;
                const uint32_t offB = (((uint32_t)(ks * 2) + uB0) ^ swB) << 4;
#pragma unroll
                for (int nj = 0; nj < 4; ++nj) {
                    ldsm4(bh[nj], sBh + nj * 16 * ROWB + offB);
                    ldsm4(bl[nj], sBl + nj * 16 * ROWB + offB);
                }
            } else {
                const uint32_t rOff = (ks * 16 + tRow) * 256;
                const uint32_t sBh = base + 2 * TILEB + rOff;
                const uint32_t sBl = sBh + TILEB;
#pragma unroll
                for (int nj = 0; nj < 4; ++nj) {
                    uint32_t u0 = (uint32_t)(warpN * 8 + nj * 2) + tHalf;
                    uint32_t so = (u0 ^ tLow) << 4;
                    ldsm4t(bh[nj], sBh + so);
                    ldsm4t(bl[nj], sBl + so);
                }
            }
            // pass hh
#pragma unroll
            for (int mi = 0; mi < 2; ++mi)
#pragma unroll
                for (int nj = 0; nj < 4; ++nj) {
                    mma16816(acc[mi][2 * nj],     ah[mi], bh[nj][0], bh[nj][1]);
                    mma16816(acc[mi][2 * nj + 1], ah[mi], bh[nj][2], bh[nj][3]);
                }
            // pass hl
#pragma unroll
            for (int mi = 0; mi < 2; ++mi)
#pragma unroll
                for (int nj = 0; nj < 4; ++nj) {
                    mma16816(acc[mi][2 * nj],     ah[mi], bl[nj][0], bl[nj][1]);
                    mma16816(acc[mi][2 * nj + 1], ah[mi], bl[nj][2], bl[nj][3]);
                }
            // pass lh
#pragma unroll
            for (int mi = 0; mi < 2; ++mi)
#pragma unroll
                for (int nj = 0; nj < 4; ++nj) {
                    mma16816(acc[mi][2 * nj],     al[mi], bh[nj][0], bh[nj][1]);
                    mma16816(acc[mi][2 * nj + 1], al[mi], bh[nj][2], bh[nj][3]);
                }
        }
    };

    loadChunk(0, 0);
    if (nt > 1) loadChunk(1, 1);
    int sidx = 0;
    for (int c = 0; c < nt; ++c) {
        cp_wait<1>();
        __syncthreads();
        compute(sidx);
        if (c + 2 < nt) {
            int ns = sidx + 2; if (ns >= STAGES) ns -= STAGES;
            loadChunk(c + 2, ns);
        }
        ++sidx; if (sidx == STAGES) sidx = 0;
    }

    // ---- epilogue ----
    const int r = lane >> 2, cq = (lane & 3) * 2;
    const int mbase = m0 + warpM * 32, nbase = n0 + warpN * 64;
#pragma unroll
    for (int mi = 0; mi < 2; ++mi) {
        float rsA = 0.f, rsB = 0.f;
#pragma unroll
        for (int nj = 0; nj < 8; ++nj) {
            int row = mbase + mi * 16 + r;
            int col = nbase + nj * 8 + cq;
            float v0 = alpha * acc[mi][nj][0];
            float v1 = alpha * acc[mi][nj][1];
            float v2 = alpha * acc[mi][nj][2];
            float v3 = alpha * acc[mi][nj][3];
            if (biasN) { float b0 = biasN[col], b1 = biasN[col + 1]; v0 += b0; v1 += b1; v2 += b0; v3 += b1; }
            if (Cf) {
                float* base = Cf + blockIdx.z * partStride;
                *reinterpret_cast<float2*>(base + (size_t)row * ldc + col)       = make_float2(v0, v1);
                *reinterpret_cast<float2*>(base + (size_t)(row + 8) * ldc + col) = make_float2(v2, v3);
            }
            if (Chi) {
                if (doExp) {
                    v0 = __expf(v0 + expShift); v1 = __expf(v1 + expShift);
                    v2 = __expf(v2 + expShift); v3 = __expf(v3 + expShift);
                    rsA += v0 + v1;
                    rsB += v2 + v3;
                }
                bf16 h0 = __float2bfloat16(v0), h1 = __float2bfloat16(v1);
                bf16 h2 = __float2bfloat16(v2), h3 = __float2bfloat16(v3);
                __nv_bfloat162 p01; p01.x = h0; p01.y = h1;
                __nv_bfloat162 p23; p23.x = h2; p23.y = h3;
                *reinterpret_cast<__nv_bfloat162*>(Chi + (size_t)row * ldc + col)       = p01;
                *reinterpret_cast<__nv_bfloat162*>(Chi + (size_t)(row + 8) * ldc + col) = p23;
                __nv_bfloat162 l01, l23;
                l01.x = __float2bfloat16(v0 - __bfloat162float(h0));
                l01.y = __float2bfloat16(v1 - __bfloat162float(h1));
                l23.x = __float2bfloat16(v2 - __bfloat162float(h2));
                l23.y = __float2bfloat16(v3 - __bfloat162float(h3));
                *reinterpret_cast<__nv_bfloat162*>(Clo + (size_t)row * ldc + col)       = l01;
                *reinterpret_cast<__nv_bfloat162*>(Clo + (size_t)(row + 8) * ldc + col) = l23;
            }
        }
        if (sums) {
            rsA += __shfl_xor_sync(0xffffffffu, rsA, 1);
            rsA += __shfl_xor_sync(0xffffffffu, rsA, 2);
            rsB += __shfl_xor_sync(0xffffffffu, rsB, 1);
            rsB += __shfl_xor_sync(0xffffffffu, rsB, 2);
            if ((lane & 3) == 0) {
                int rowA = mbase + mi * 16 + r;
                atomicAdd(&sums[rowA], rsA);
                atomicAdd(&sums[rowA + 8], rsB);
            }
        }
    }
}

// ---------------------------------------------------------------------------
// fp32 SIMT NT GEMM for the small 512x512 products (Km, Vt); optional bf16
// hi/lo pair output alongside the fp32 result.
// ---------------------------------------------------------------------------
__global__ __launch_bounds__(256, 2)
void gemm_nt(const float* __restrict__ A, const float* __restrict__ B, int K1,
             const float* __restrict__ A2, const float* __restrict__ B2, int K2,
             float* __restrict__ C, int ldc, float alpha,
             const float* __restrict__ biasN, const float* __restrict__ biasN2,
             const float* __restrict__ biasM,
             bf16* __restrict__ Chi, bf16* __restrict__ Clo)
{
    __shared__ float As[2][8][128];
    __shared__ float Bs[2][8][128];
    const int tid = threadIdx.x;
    const int m0 = blockIdx.y * 128, n0 = blockIdx.x * 128;
    const int lrow = tid >> 1, lk = (tid & 1) * 4;
    const int ty = tid >> 4, tx = tid & 15;

    float acc[8][8];
#pragma unroll
    for (int i = 0; i < 8; ++i)
#pragma unroll
        for (int j = 0; j < 8; ++j) acc[i][j] = 0.f;

    const int nk1 = K1 >> 3;
    const int nk2 = A2 ? (K2 >> 3) : 0;
    const int nkt = nk1 + nk2;

    float4 ra, rb;
    auto load_t = [&](int t) {
        if (t < nk1) {
            ra = *reinterpret_cast<const float4*>(A + (size_t)(m0 + lrow) * K1 + (t << 3) + lk);
            rb = *reinterpret_cast<const float4*>(B + (size_t)(n0 + lrow) * K1 + (t << 3) + lk);
        } else {
            int u = t - nk1;
            ra = *reinterpret_cast<const float4*>(A2 + (size_t)(m0 + lrow) * K2 + (u << 3) + lk);
            rb = *reinterpret_cast<const float4*>(B2 + (size_t)(n0 + lrow) * K2 + (u << 3) + lk);
        }
    };

    load_t(0);
    As[0][lk+0][lrow]=ra.x; As[0][lk+1][lrow]=ra.y; As[0][lk+2][lrow]=ra.z; As[0][lk+3][lrow]=ra.w;
    Bs[0][lk+0][lrow]=rb.x; Bs[0][lk+1][lrow]=rb.y; Bs[0][lk+2][lrow]=rb.z; Bs[0][lk+3][lrow]=rb.w;
    __syncthreads();

    int cur = 0;
    for (int t = 0; t < nkt; ++t) {
        const bool more = (t + 1 < nkt);
        if (more) load_t(t + 1);
        const float(*Asc)[128] = As[cur];
        const float(*Bsc)[128] = Bs[cur];
#pragma unroll
        for (int kk = 0; kk < 8; ++kk) {
            float4 a0 = *reinterpret_cast<const float4*>(&Asc[kk][ty << 2]);
            float4 a1 = *reinterpret_cast<const float4*>(&Asc[kk][(ty << 2) + 64]);
            float4 b0 = *reinterpret_cast<const float4*>(&Bsc[kk][tx << 2]);
            float4 b1 = *reinterpret_cast<const float4*>(&Bsc[kk][(tx << 2) + 64]);
            float av[8] = {a0.x,a0.y,a0.z,a0.w,a1.x,a1.y,a1.z,a1.w};
            float bv[8] = {b0.x,b0.y,b0.z,b0.w,b1.x,b1.y,b1.z,b1.w};
#pragma unroll
            for (int i = 0; i < 8; ++i)
#pragma unroll
                for (int j = 0; j < 8; ++j) acc[i][j] += av[i] * bv[j];
        }
        if (more) {
            int nxt = cur ^ 1;
            As[nxt][lk+0][lrow]=ra.x; As[nxt][lk+1][lrow]=ra.y; As[nxt][lk+2][lrow]=ra.z; As[nxt][lk+3][lrow]=ra.w;
            Bs[nxt][lk+0][lrow]=rb.x; Bs[nxt][lk+1][lrow]=rb.y; Bs[nxt][lk+2][lrow]=rb.z; Bs[nxt][lk+3][lrow]=rb.w;
            __syncthreads();
            cur = nxt;
        }
    }
#pragma unroll
    for (int ii = 0; ii < 2; ++ii)
#pragma unroll
        for (int i = 0; i < 4; ++i) {
            int row = m0 + ii * 64 + (ty << 2) + i;
            float bm = biasM ? biasM[row] : 0.f;
#pragma unroll
            for (int jj = 0; jj < 2; ++jj)
#pragma unroll
                for (int j = 0; j < 4; ++j) {
                    int col = n0 + jj * 64 + (tx << 2) + j;
                    float v = alpha * acc[ii * 4 + i][jj * 4 + j] + bm;
                    if (biasN)  v += biasN[col];
                    if (biasN2) v += biasN2[col];
                    C[(size_t)row * ldc + col] = v;
                    if (Chi) {
                        bf16 h = __float2bfloat16(v);
                        Chi[(size_t)row * ldc + col] = h;
                        Clo[(size_t)row * ldc + col] = __float2bfloat16(v - __bfloat162float(h));
                    }
                }
        }
}

// ---------------------------------------------------------------------------
// fp32 SIMT NN GEMM (512x512x512): C = A·Bz, bf16 hi/lo pair out.
// blockIdx.z picks (B1sel, C1) vs (B2sel, C2).
// ---------------------------------------------------------------------------
__global__ __launch_bounds__(256, 2)
void gemm_nn_pair2(const float* __restrict__ A,
                   const float* __restrict__ Ba, const float* __restrict__ Bb,
                   bf16* __restrict__ C1h, bf16* __restrict__ C1l,
                   bf16* __restrict__ C2h, bf16* __restrict__ C2l)
{
    const float* B = blockIdx.z ? Bb : Ba;
    bf16* Chi = blockIdx.z ? C2h : C1h;
    bf16* Clo = blockIdx.z ? C2l : C1l;

    __shared__ float As[2][8][128];
    __shared__ float Bs[2][8][128];
    const int tid = threadIdx.x;
    const int m0 = blockIdx.y * 128, n0 = blockIdx.x * 128;
    const int lrow = tid >> 1, lk = (tid & 1) * 4;
    const int bk = tid >> 5, bc = (tid & 31) * 4;
    const int ty = tid >> 4, tx = tid & 15;

    float acc[8][8];
#pragma unroll
    for (int i = 0; i < 8; ++i)
#pragma unroll
        for (int j = 0; j < 8; ++j) acc[i][j] = 0.f;

    const int nkt = DIM / 8;

    float4 ra, rb;
    auto load_t = [&](int t) {
        int kb = t << 3;
        ra = *reinterpret_cast<const float4*>(A + (size_t)(m0 + lrow) * DIM + kb + lk);
        rb = *reinterpret_cast<const float4*>(B + (size_t)(kb + bk) * DIM + n0 + bc);
    };

    load_t(0);
    As[0][lk+0][lrow]=ra.x; As[0][lk+1][lrow]=ra.y; As[0][lk+2][lrow]=ra.z; As[0][lk+3][lrow]=ra.w;
    *reinterpret_cast<float4*>(&Bs[0][bk][bc]) = rb;
    __syncthreads();

    int cur = 0;
    for (int t = 0; t < nkt; ++t) {
        const bool more = (t + 1 < nkt);
        if (more) load_t(t + 1);
        const float(*Asc)[128] = As[cur];
        const float(*Bsc)[128] = Bs[cur];
#pragma unroll
        for (int kk = 0; kk < 8; ++kk) {
            float4 a0 = *reinterpret_cast<const float4*>(&Asc[kk][ty << 2]);
            float4 a1 = *reinterpret_cast<const float4*>(&Asc[kk][(ty << 2) + 64]);
            float4 b0 = *reinterpret_cast<const float4*>(&Bsc[kk][tx << 2]);
            float4 b1 = *reinterpret_cast<const float4*>(&Bsc[kk][(tx << 2) + 64]);
            float av[8] = {a0.x,a0.y,a0.z,a0.w,a1.x,a1.y,a1.z,a1.w};
            float bv[8] = {b0.x,b0.y,b0.z,b0.w,b1.x,b1.y,b1.z,b1.w};
#pragma unroll
            for (int i = 0; i < 8; ++i)
#pragma unroll
                for (int j = 0; j < 8; ++j) acc[i][j] += av[i] * bv[j];
        }
        if (more) {
            int nxt = cur ^ 1;
            As[nxt][lk+0][lrow]=ra.x; As[nxt][lk+1][lrow]=ra.y; As[nxt][lk+2][lrow]=ra.z; As[nxt][lk+3][lrow]=ra.w;
            *reinterpret_cast<float4*>(&Bs[nxt][bk][bc]) = rb;
            __syncthreads();
            cur = nxt;
        }
    }
#pragma unroll
    for (int ii = 0; ii < 2; ++ii)
#pragma unroll
        for (int i = 0; i < 4; ++i) {
            int row = m0 + ii * 64 + (ty << 2) + i;
#pragma unroll
            for (int jj = 0; jj < 2; ++jj)
#pragma unroll
                for (int j = 0; j < 4; ++j) {
                    int col = n0 + jj * 64 + (tx << 2) + j;
                    float v = acc[ii * 4 + i][jj * 4 + j];
                    bf16 h = __float2bfloat16(v);
                    Chi[(size_t)row * DIM + col] = h;
                    Clo[(size_t)row * DIM + col] = __float2bfloat16(v - __bfloat162float(h));
                }
        }
}

// biasK[m] = SCALE * sum_d (bq[d]+bgp[d]) * Km[m,d]   (warp per row)
__global__ void biask_kernel(const float* __restrict__ Km, const float* __restrict__ bq,
                             const float* __restrict__ bgp, float* __restrict__ biasK)
{
    const int warp = threadIdx.x >> 5;
    const int lane = threadIdx.x & 31;
    const int row = blockIdx.x * 8 + warp;
    float s = 0.f;
#pragma unroll
    for (int j = 0; j < 16; ++j) {
        int d = lane + 32 * j;
        s += (bq[d] + bgp[d]) * Km[row * DIM + d];
    }
#pragma unroll
    for (int o = 16; o; o >>= 1) s += __shfl_xor_sync(0xffffffffu, s, o);
    if (lane == 0) biasK[row] = ATT_SCALE * s;
}

// kp[m,d] = (sum_z parts[z][m,d]) / sums1[m]   (deferred pool normalization)
__global__ void reduce_parts(const float* __restrict__ parts, const float* __restrict__ sums1,
                             float* __restrict__ kp)
{
    int i = blockIdx.x * 256 + threadIdx.x;
    float s = 0.f;
#pragma unroll
    for (int z = 0; z < ZSL; ++z)
        s += parts[(size_t)z * (MTOK * DIM) + i];
    kp[i] = s / sums1[i >> 9];   // DIM = 512
}

__global__ void convert_pair(const float* __restrict__ x, bf16* __restrict__ h,
                             bf16* __restrict__ l, int n)
{
    int i = (blockIdx.x * 256 + threadIdx.x) * 4;
    if (i >= n) return;
    float4 v = *reinterpret_cast<const float4*>(x + i);
    bf16 h0 = __float2bfloat16(v.x), h1 = __float2bfloat16(v.y);
    bf16 h2 = __float2bfloat16(v.z), h3 = __float2bfloat16(v.w);
    __nv_bfloat162 a, b; a.x = h0; a.y = h1; b.x = h2; b.y = h3;
    reinterpret_cast<__nv_bfloat162*>(h + i)[0] = a;
    reinterpret_cast<__nv_bfloat162*>(h + i)[1] = b;
    __nv_bfloat162 c, d;
    c.x = __float2bfloat16(v.x - __bfloat162float(h0));
    c.y = __float2bfloat16(v.y - __bfloat162float(h1));
    d.x = __float2bfloat16(v.z - __bfloat162float(h2));
    d.y = __float2bfloat16(v.w - __bfloat162float(h3));
    reinterpret_cast<__nv_bfloat162*>(l + i)[0] = c;
    reinterpret_cast<__nv_bfloat162*>(l + i)[1] = d;
}

// out = LayerNorm(OP/sum + g) * gamma + beta (warp per row)
__global__ void add_ln(const float* __restrict__ OP, const float* __restrict__ G,
                       const float* __restrict__ sums,
                       const float* __restrict__ gamma, const float* __restrict__ beta,
                       float* __restrict__ out)
{
    const int warp = threadIdx.x >> 5;
    const int lane = threadIdx.x & 31;
    const size_t row = (size_t)blockIdx.x * 8 + warp;
    const float4* po = reinterpret_cast<const float4*>(OP + row * DIM);
    const float4* pg = reinterpret_cast<const float4*>(G + row * DIM);
    float4* pw = reinterpret_cast<float4*>(out + row * DIM);
    const float inv = 1.0f / sums[row];

    float4 x[4];
    float s1 = 0.f, s2 = 0.f;
#pragma unroll
    for (int j = 0; j < 4; ++j) {
        float4 a = po[lane + 32 * j];
        float4 b = pg[lane + 32 * j];
        a.x = a.x * inv + b.x; a.y = a.y * inv + b.y;
        a.z = a.z * inv + b.z; a.w = a.w * inv + b.w;
        x[j] = a;
        s1 += (a.x + a.y) + (a.z + a.w);
        s2 += (a.x * a.x + a.y * a.y) + (a.z * a.z + a.w * a.w);
    }
#pragma unroll
    for (int o = 16; o; o >>= 1) {
        s1 += __shfl_xor_sync(0xffffffffu, s1, o);
        s2 += __shfl_xor_sync(0xffffffffu, s2, o);
    }
    const float mu = s1 * (1.0f / DIM);
    const float var = s2 * (1.0f / DIM) - mu * mu;
    const float rs = rsqrtf(var + 1e-5f);
    const float4* pgm = reinterpret_cast<const float4*>(gamma);
    const float4* pbt = reinterpret_cast<const float4*>(beta);
#pragma unroll
    for (int j = 0; j < 4; ++j) {
        float4 gm = pgm[lane + 32 * j];
        float4 bt = pbt[lane + 32 * j];
        float4 o4;
        o4.x = (x[j].x - mu) * rs * gm.x + bt.x;
        o4.y = (x[j].y - mu) * rs * gm.y + bt.y;
        o4.z = (x[j].z - mu) * rs * gm.z + bt.z;
        o4.w = (x[j].w - mu) * rs * gm.w + bt.w;
        pw[lane + 32 * j] = o4;
    }
}

// ---------------------------------------------------------------------------
extern "C" void kernel_launch(void* const* d_in, const int* in_sizes, int n_in,
                              void* d_out, int out_size)
{
    const float* g   = (const float*)d_in[0];
    const float* g_p = (const float*)d_in[1];
    const float* W   = (const float*)d_in[2];
    const float* Wq  = (const float*)d_in[3];
    const float* bq  = (const float*)d_in[4];
    const float* Wk  = (const float*)d_in[5];
    const float* bk  = (const float*)d_in[6];
    const float* Wv  = (const float*)d_in[7];
    const float* bv  = (const float*)d_in[8];
    const float* Wgp = (const float*)d_in[9];
    const float* bgp = (const float*)d_in[10];
    const float* Wkp = (const float*)d_in[11];
    const float* bkp = (const float*)d_in[12];
    const float* gam = (const float*)d_in[13];
    const float* bet = (const float*)d_in[14];
    float* out = (float*)d_out;

    float *OP, *parts, *kp, *Km, *Vt, *sums, *sums1, *biasK;
    bf16 *gh,*gl,*gph,*gpl,*Ph,*Pl;
    bf16 *Wsh,*Wsl,*B1h,*B1l,*B2h,*B2l,*Vth,*Vtl;
    cudaGetSymbolAddress((void**)&OP, d_OP);
    cudaGetSymbolAddress((void**)&parts, d_parts); cudaGetSymbolAddress((void**)&kp, d_kp);
    cudaGetSymbolAddress((void**)&Km, d_Km);     cudaGetSymbolAddress((void**)&Vt, d_Vt);
    cudaGetSymbolAddress((void**)&sums, d_sums); cudaGetSymbolAddress((void**)&sums1, d_sums1);
    cudaGetSymbolAddress((void**)&biasK, d_biasK);
    cudaGetSymbolAddress((void**)&gh, d_gh);     cudaGetSymbolAddress((void**)&gl, d_gl);
    cudaGetSymbolAddress((void**)&gph, d_gph);   cudaGetSymbolAddress((void**)&gpl, d_gpl);
    cudaGetSymbolAddress((void**)&Ph, d_Ph);     cudaGetSymbolAddress((void**)&Pl, d_Pl);
    cudaGetSymbolAddress((void**)&Wsh, d_Wsh);   cudaGetSymbolAddress((void**)&Wsl, d_Wsl);
    cudaGetSymbolAddress((void**)&B1h, d_B1h);   cudaGetSymbolAddress((void**)&B1l, d_B1l);
    cudaGetSymbolAddress((void**)&B2h, d_B2h);   cudaGetSymbolAddress((void**)&B2l, d_B2l);
    cudaGetSymbolAddress((void**)&Vth, d_Vth);   cudaGetSymbolAddress((void**)&Vtl, d_Vtl);

    cudaFuncSetAttribute(gemm3, cudaFuncAttributeMaxDynamicSharedMemorySize, GEMM_SMEM);

    const int NGD = NG * DIM;
    // aux (no transpose needed anymore: kp GEMM consumes gph/gpl k-major)
    cudaMemsetAsync(sums, 0, NG * sizeof(float));
    cudaMemsetAsync(sums1, 0, MTOK * sizeof(float));
    convert_pair<<<NGD / 1024, 256>>>(g, gh, gl, NGD);
    convert_pair<<<NGD / 1024, 256>>>(g_p, gph, gpl, NGD);
    convert_pair<<<(MTOK * DIM) / 1024, 256>>>(W, Wsh, Wsl, MTOK * DIM);

    // expS1 = exp(Ws·g^T - 100) -> bf16 pair + atomic row sums (sums1).
    gemm3<<<dim3(MTOK / 128, NG / 128, 1), 256, GEMM_SMEM>>>(
        Wsh, Wsl, gh, gl, DIM, nullptr, nullptr, nullptr, nullptr, 0,
        nullptr, NG, 1.0f, nullptr, Ph, Pl, 1, POOL_SHIFT, sums1, 1, 0, 0, DIM, 0);
    // kp_un = expS1 · g_p  (NN mode: B = gph/gpl k-major, ldbT = DIM;
    // split-K over 16 slices -> 256 blocks = 1 clean wave)
    gemm3<<<dim3(DIM / 128, MTOK / 128, ZSL), 256, GEMM_SMEM>>>(
        Ph, Pl, gph, gpl, NG, nullptr, nullptr, nullptr, nullptr, 0,
        parts, DIM, 1.0f, nullptr, nullptr, nullptr, 0, 0.f, nullptr, 0, 1, DIM,
        KSL, (size_t)MTOK * DIM);
    // kp = (sum parts) / sums1   (deferred pool normalization)
    reduce_parts<<<(MTOK * DIM) / 256, 256>>>(parts, sums1, kp);
    // K = Ws·Wk^T + kp·Wkp^T + bk + bkp   (small, fp32)
    gemm_nt<<<dim3(4, 4), 256>>>(W, Wk, DIM, kp, Wkp, DIM, Km, DIM, 1.0f, bk, bkp, nullptr,
                                 nullptr, nullptr);
    // Vt[d,m] = (Wv·Ws^T)[d,m] + bv[d]  -> fp32 + bf16 pair fused
    gemm_nt<<<dim3(4, 4), 256>>>(Wv, W, DIM, nullptr, nullptr, 0, Vt, MTOK, 1.0f,
                                 nullptr, nullptr, bv, Vth, Vtl);
    // B1 = K·Wq, B2 = K·Wgp (bf16 pair, one launch); biasK = SCALE*(bq+bgp)·K^T
    gemm_nn_pair2<<<dim3(4, 4, 2), 256>>>(Km, Wq, Wgp, B1h, B1l, B2h, B2l);
    biask_kernel<<<MTOK / 8, 256>>>(Km, bq, bgp, biasK);
    // expS2 = exp(SCALE*(g·B1^T + gp·B2^T) + biasK) -> bf16 pair + row sums
    gemm3<<<dim3(MTOK / 128, NG / 128, 1), 256, GEMM_SMEM>>>(
        gh, gl, B1h, B1l, DIM, gph, gpl, B2h, B2l, DIM,
        nullptr, MTOK, ATT_SCALE, biasK, Ph, Pl, 1, 0.f, sums, 0, 0, 0, DIM, 0);
    // OP = expS2 · V (unnormalized; NT with Vt)
    gemm3<<<dim3(DIM / 128, NG / 128, 1), 256, GEMM_SMEM>>>(
        Ph, Pl, Vth, Vtl, MTOK, nullptr, nullptr, nullptr, nullptr, 0,
        OP, DIM, 1.0f, nullptr, nullptr, nullptr, 0, 0.f, nullptr, 0, 0, 0, MTOK, 0);
    // out = LN(OP/sum + g)
    add_ln<<<NG / 8, 256>>>(OP, g, sums, gam, bet, out);
}

// round 16
// speedup vs baseline: 1.0550x; 1.0550x over previous
#include <cuda_runtime.h>
#include <cuda_bf16.h>
#include <stdint.h>
#include <math.h>

typedef __nv_bfloat16 bf16;

#define DIM   512
#define MTOK  512
#define NG    65536
#define ATT_SCALE 0.125f
#define POOL_SHIFT (-100.0f)
#define ZSL   16
#define KSL   (NG / ZSL)            // 4096

// SMEM: K-chunk 32. NT tiles: 128 rows x 64B (XOR swizzle q^((r>>1)&3)).
// Trans-B tiles: 32 k-rows x 256B (XOR swizzle q^(r&7)). Both 8KB.
#define ROWB 64
#define TILEB (128 * ROWB)          // 8192
#define STAGEB (4 * TILEB)          // 32768: Ah | Al | Bh | Bl
#define STAGES 3
#define GEMM_SMEM (STAGES * STAGEB) // 98304  -> 2 CTAs per SM

// ---------------- scratch (device globals; no allocations allowed) ----------
__device__ float d_OP[(size_t)NG * DIM];
__device__ float d_parts[(size_t)ZSL * MTOK * DIM];
__device__ float d_kp[MTOK * DIM];
__device__ float d_Km[MTOK * DIM];
__device__ float d_Vt[DIM * MTOK];
__device__ float d_sums[NG];
__device__ float d_sums1[MTOK];
__device__ float d_biasK[MTOK];
__device__ bf16 d_gh[(size_t)NG * DIM],   d_gl[(size_t)NG * DIM];
__device__ bf16 d_gph[(size_t)NG * DIM],  d_gpl[(size_t)NG * DIM];
__device__ bf16 d_Ph[(size_t)NG * MTOK],  d_Pl[(size_t)NG * MTOK];
__device__ bf16 d_Wsh[MTOK * DIM], d_Wsl[MTOK * DIM];
__device__ bf16 d_B1h[MTOK * DIM], d_B1l[MTOK * DIM];
__device__ bf16 d_B2h[MTOK * DIM], d_B2l[MTOK * DIM];
__device__ bf16 d_Vth[DIM * MTOK], d_Vtl[DIM * MTOK];

// ---------------- helpers ----------------
__device__ __forceinline__ uint32_t smem_u32(const void* p) {
    uint32_t a;
    asm("{ .reg .u64 t; cvta.to.shared.u64 t, %1; cvt.u32.u64 %0, t; }" : "=r"(a) : "l"(p));
    return a;
}
__device__ __forceinline__ void ldsm4(uint32_t* r, uint32_t addr) {
    asm volatile("ldmatrix.sync.aligned.m8n8.x4.shared.b16 {%0,%1,%2,%3}, [%4];"
        : "=r"(r[0]), "=r"(r[1]), "=r"(r[2]), "=r"(r[3]) : "r"(addr));
}
__device__ __forceinline__ void ldsm4t(uint32_t* r, uint32_t addr) {
    asm volatile("ldmatrix.sync.aligned.m8n8.x4.trans.shared.b16 {%0,%1,%2,%3}, [%4];"
        : "=r"(r[0]), "=r"(r[1]), "=r"(r[2]), "=r"(r[3]) : "r"(addr));
}
__device__ __forceinline__ void mma16816(float* c, const uint32_t* a, uint32_t b0, uint32_t b1) {
    asm volatile("mma.sync.aligned.m16n8k16.row.col.f32.bf16.bf16.f32 "
        "{%0,%1,%2,%3}, {%4,%5,%6,%7}, {%8,%9}, {%0,%1,%2,%3};"
        : "+f"(c[0]), "+f"(c[1]), "+f"(c[2]), "+f"(c[3])
        : "r"(a[0]), "r"(a[1]), "r"(a[2]), "r"(a[3]), "r"(b0), "r"(b1));
}
__device__ __forceinline__ void cp16(uint32_t saddr, const void* gaddr) {
    asm volatile("cp.async.cg.shared.global [%0], [%1], 16;" :: "r"(saddr), "l"(gaddr));
}
__device__ __forceinline__ void cp_commit() { asm volatile("cp.async.commit_group;"); }
template<int N> __device__ __forceinline__ void cp_wait() {
    asm volatile("cp.async.wait_group %0;" :: "n"(N) : "memory");
}

// ---------------------------------------------------------------------------
// bf16x3 GEMM via mma.sync. 128x128 tile, 8 warps (32x64 warp tiles),
// K-chunks of 32, XOR-swizzled SMEM (2 CTAs/SM), 3-stage pipeline, single
// sync per chunk, ks-outer fragment reuse. BTRANS is compile-time so the NT
// instantiation carries zero branch/indexing overhead.
// NT (BTRANS=0): C = alpha*(A1·B1^T + A2·B2^T) + biasN, B row-major [n,k].
// NN (BTRANS=1): B1 is [k, n] with row stride ldbT (single source only).
// Output fp32 and/or bf16 hi/lo pair; doExp: v=exp(v+expShift) before pair
// output; sums gets atomic row sums. swapXY=1: m-tile on blockIdx.x.
// ---------------------------------------------------------------------------
template<int BTRANS>
__global__ void __launch_bounds__(256, 2)
gemm3(const bf16* __restrict__ A1h, const bf16* __restrict__ A1l,
      const bf16* __restrict__ B1h, const bf16* __restrict__ B1l, int K1,
      const bf16* __restrict__ A2h, const bf16* __restrict__ A2l,
      const bf16* __restrict__ B2h, const bf16* __restrict__ B2l, int K2,
      float* __restrict__ Cf, int ldc, float alpha,
      const float* __restrict__ biasN,
      bf16* __restrict__ Chi, bf16* __restrict__ Clo, int doExp, float expShift,
      float* __restrict__ sums, int swapXY, int ldbT,
      int kslice, size_t partStride)
{
    extern __shared__ __align__(16) char smem[];
    const uint32_t sb = smem_u32(smem);
    const int tid = threadIdx.x, lane = tid & 31, wid = tid >> 5;
    const int warpM = wid & 3, warpN = wid >> 2;
    const int m0 = (swapXY ? blockIdx.x : blockIdx.y) * 128;
    const int n0 = (swapXY ? blockIdx.y : blockIdx.x) * 128;
    const int k0 = blockIdx.z * kslice;

    const int nk1 = kslice >> 5;
    const int nk2 = A2h ? (K2 >> 5) : 0;
    const int nt = nk1 + nk2;

    float acc[2][8][4];
#pragma unroll
    for (int i = 0; i < 2; ++i)
#pragma unroll
        for (int j = 0; j < 8; ++j)
#pragma unroll
            for (int q = 0; q < 4; ++q) acc[i][j][q] = 0.f;

    auto loadChunk = [&](int c, int s) {
        const bf16 *Ah, *Al, *Bh, *Bl; int K, kb;
        if (c < nk1) { Ah = A1h; Al = A1l; Bh = B1h; Bl = B1l; K = K1; kb = k0 + (c << 5); }
        else         { Ah = A2h; Al = A2l; Bh = B2h; Bl = B2l; K = K2; kb = (c - nk1) << 5; }
        const uint32_t base = sb + s * STAGEB;
        if (!BTRANS) {
#pragma unroll
            for (int i = 0; i < 8; ++i) {
                int idx = (i << 8) + tid;            // 0..2047
                int tile = idx >> 9;                 // 0..3
                int rem = idx & 511;
                int row = rem >> 2, q = rem & 3;
                int sw = q ^ ((row >> 1) & 3);
                uint32_t so = base + tile * TILEB + row * ROWB + sw * 16;
                const bf16* src;
                if      (tile == 0) src = Ah + (size_t)(m0 + row) * (size_t)K;
                else if (tile == 1) src = Al + (size_t)(m0 + row) * (size_t)K;
                else if (tile == 2) src = Bh + (size_t)(n0 + row) * (size_t)K;
                else                src = Bl + (size_t)(n0 + row) * (size_t)K;
                cp16(so, src + (size_t)(kb + q * 8));
            }
        } else {
            // A tiles: unchanged (128 rows x 4 units, NT layout)
#pragma unroll
            for (int i = 0; i < 4; ++i) {
                int idx = (i << 8) + tid;            // 0..1023
                int tile = idx >> 9;                 // 0..1
                int rem = idx & 511;
                int row = rem >> 2, q = rem & 3;
                int sw = q ^ ((row >> 1) & 3);
                uint32_t so = base + tile * TILEB + row * ROWB + sw * 16;
                const bf16* src = (tile ? Al : Ah) + (size_t)(m0 + row) * (size_t)K;
                cp16(so, src + (size_t)(kb + q * 8));
            }
            // B tiles: k-major [32 k-rows x 128 n-cols], row = 256B = 16 units,
            // swizzle q^(row&7)
#pragma unroll
            for (int i = 0; i < 4; ++i) {
                int idx = (i << 8) + tid;            // 0..1023
                int tile = idx >> 9;                 // 0..1
                int rem = idx & 511;
                int row = rem >> 4, q = rem & 15;    // 32 rows x 16 units
                int sw = q ^ (row & 7);
                uint32_t so = base + (2 + tile) * TILEB + row * 256 + sw * 16;
                const bf16* src = (tile ? B1l : B1h) + (size_t)(kb + row) * (size_t)ldbT;
                cp16(so, src + (size_t)(n0 + q * 8));
            }
        }
        cp_commit();
    };

    const uint32_t nrow = (((uint32_t)lane >> 4) << 3) + (lane & 7);
    const uint32_t aRowOff = (uint32_t)(warpM * 32 + (lane & 15)) * ROWB;
    const uint32_t bRowOff = (uint32_t)(warpN * 64 + nrow) * ROWB;
    const uint32_t swA = (((uint32_t)lane & 15) >> 1) & 3;
    const uint32_t swB = (nrow >> 1) & 3;
    const uint32_t uA0 = (uint32_t)lane >> 4;          // k-half select for A
    const uint32_t uB0 = ((uint32_t)lane >> 3) & 1;    // k-half select for B
    // trans-B read geometry: row = ks*16 + (lane&15); per nj:
    // u0 = warpN*8 + nj*2 + (lane>>4), sw = u0 ^ (lane&7)  (ks*16 % 8 == 0)
    const uint32_t tRow = (uint32_t)lane & 15;
    const uint32_t tHalf = (uint32_t)lane >> 4;
    const uint32_t tLow = (uint32_t)lane & 7;

    auto compute = [&](int s) {
        const uint32_t base = sb + s * STAGEB;
        const uint32_t sAh = base + aRowOff;
        const uint32_t sAl = sAh + TILEB;
#pragma unroll
        for (int ks = 0; ks < 2; ++ks) {
            const uint32_t offA = (((uint32_t)(ks * 2) + uA0) ^ swA) << 4;
            uint32_t ah[2][4], al[2][4];
#pragma unroll
            for (int mi = 0; mi < 2; ++mi) {
                ldsm4(ah[mi], sAh + mi * 16 * ROWB + offA);
                ldsm4(al[mi], sAl + mi * 16 * ROWB + offA);
            }
            uint32_t bh[4][4], bl[4][4];
            if (!BTRANS) {
                const uint32_t sBh = base + 2 * TILEB + bRowOff;
                const uint32_t sBl = sBh + TILEB;
                const uint32_t offB = (((uint32_t)(ks * 2) + uB0) ^ swB) << 4;
#pragma unroll
                for (int nj = 0; nj < 4; ++nj) {
                    ldsm4(bh[nj], sBh + nj * 16 * ROWB + offB);
                    ldsm4(bl[nj], sBl + nj * 16 * ROWB + offB);
                }
            } else {
                const uint32_t rOff = (ks * 16 + tRow) * 256;
                const uint32_t sBh = base + 2 * TILEB + rOff;
                const uint32_t sBl = sBh + TILEB;
#pragma unroll
                for (int nj = 0; nj < 4; ++nj) {
                    uint32_t u0 = (uint32_t)(warpN * 8 + nj * 2) + tHalf;
                    uint32_t so = (u0 ^ tLow) << 4;
                    ldsm4t(bh[nj], sBh + so);
                    ldsm4t(bl[nj], sBl + so);
                }
            }
            // pass hh
#pragma unroll
            for (int mi = 0; mi < 2; ++mi)
#pragma unroll
                for (int nj = 0; nj < 4; ++nj) {
                    mma16816(acc[mi][2 * nj],     ah[mi], bh[nj][0], bh[nj][1]);
                    mma16816(acc[mi][2 * nj + 1], ah[mi], bh[nj][2], bh[nj][3]);
                }
            // pass hl
#pragma unroll
            for (int mi = 0; mi < 2; ++mi)
#pragma unroll
                for (int nj = 0; nj < 4; ++nj) {
                    mma16816(acc[mi][2 * nj],     ah[mi], bl[nj][0], bl[nj][1]);
                    mma16816(acc[mi][2 * nj + 1], ah[mi], bl[nj][2], bl[nj][3]);
                }
            // pass lh
#pragma unroll
            for (int mi = 0; mi < 2; ++mi)
#pragma unroll
                for (int nj = 0; nj < 4; ++nj) {
                    mma16816(acc[mi][2 * nj],     al[mi], bh[nj][0], bh[nj][1]);
                    mma16816(acc[mi][2 * nj + 1], al[mi], bh[nj][2], bh[nj][3]);
                }
        }
    };

    loadChunk(0, 0);
    if (nt > 1) loadChunk(1, 1);
    int sidx = 0;
    for (int c = 0; c < nt; ++c) {
        cp_wait<1>();
        __syncthreads();
        compute(sidx);
        if (c + 2 < nt) {
            int ns = sidx + 2; if (ns >= STAGES) ns -= STAGES;
            loadChunk(c + 2, ns);
        }
        ++sidx; if (sidx == STAGES) sidx = 0;
    }

    // ---- epilogue ----
    const int r = lane >> 2, cq = (lane & 3) * 2;
    const int mbase = m0 + warpM * 32, nbase = n0 + warpN * 64;
#pragma unroll
    for (int mi = 0; mi < 2; ++mi) {
        float rsA = 0.f, rsB = 0.f;
#pragma unroll
        for (int nj = 0; nj < 8; ++nj) {
            int row = mbase + mi * 16 + r;
            int col = nbase + nj * 8 + cq;
            float v0 = alpha * acc[mi][nj][0];
            float v1 = alpha * acc[mi][nj][1];
            float v2 = alpha * acc[mi][nj][2];
            float v3 = alpha * acc[mi][nj][3];
            if (biasN) { float b0 = biasN[col], b1 = biasN[col + 1]; v0 += b0; v1 += b1; v2 += b0; v3 += b1; }
            if (Cf) {
                float* base = Cf + blockIdx.z * partStride;
                *reinterpret_cast<float2*>(base + (size_t)row * ldc + col)       = make_float2(v0, v1);
                *reinterpret_cast<float2*>(base + (size_t)(row + 8) * ldc + col) = make_float2(v2, v3);
            }
            if (Chi) {
                if (doExp) {
                    v0 = __expf(v0 + expShift); v1 = __expf(v1 + expShift);
                    v2 = __expf(v2 + expShift); v3 = __expf(v3 + expShift);
                    rsA += v0 + v1;
                    rsB += v2 + v3;
                }
                bf16 h0 = __float2bfloat16(v0), h1 = __float2bfloat16(v1);
                bf16 h2 = __float2bfloat16(v2), h3 = __float2bfloat16(v3);
                __nv_bfloat162 p01; p01.x = h0; p01.y = h1;
                __nv_bfloat162 p23; p23.x = h2; p23.y = h3;
                *reinterpret_cast<__nv_bfloat162*>(Chi + (size_t)row * ldc + col)       = p01;
                *reinterpret_cast<__nv_bfloat162*>(Chi + (size_t)(row + 8) * ldc + col) = p23;
                __nv_bfloat162 l01, l23;
                l01.x = __float2bfloat16(v0 - __bfloat162float(h0));
                l01.y = __float2bfloat16(v1 - __bfloat162float(h1));
                l23.x = __float2bfloat16(v2 - __bfloat162float(h2));
                l23.y = __float2bfloat16(v3 - __bfloat162float(h3));
                *reinterpret_cast<__nv_bfloat162*>(Clo + (size_t)row * ldc + col)       = l01;
                *reinterpret_cast<__nv_bfloat162*>(Clo + (size_t)(row + 8) * ldc + col) = l23;
            }
        }
        if (sums) {
            rsA += __shfl_xor_sync(0xffffffffu, rsA, 1);
            rsA += __shfl_xor_sync(0xffffffffu, rsA, 2);
            rsB += __shfl_xor_sync(0xffffffffu, rsB, 1);
            rsB += __shfl_xor_sync(0xffffffffu, rsB, 2);
            if ((lane & 3) == 0) {
                int rowA = mbase + mi * 16 + r;
                atomicAdd(&sums[rowA], rsA);
                atomicAdd(&sums[rowA + 8], rsB);
            }
        }
    }
}

// explicit instantiations
template __global__ void gemm3<0>(const bf16*, const bf16*, const bf16*, const bf16*, int,
    const bf16*, const bf16*, const bf16*, const bf16*, int, float*, int, float,
    const float*, bf16*, bf16*, int, float, float*, int, int, int, size_t);
template __global__ void gemm3<1>(const bf16*, const bf16*, const bf16*, const bf16*, int,
    const bf16*, const bf16*, const bf16*, const bf16*, int, float*, int, float,
    const float*, bf16*, bf16*, int, float, float*, int, int, int, size_t);

// ---------------------------------------------------------------------------
// fp32 SIMT NT GEMM for the small 512x512 products (Km, Vt); optional bf16
// hi/lo pair output alongside the fp32 result.
// ---------------------------------------------------------------------------
__global__ __launch_bounds__(256, 2)
void gemm_nt(const float* __restrict__ A, const float* __restrict__ B, int K1,
             const float* __restrict__ A2, const float* __restrict__ B2, int K2,
             float* __restrict__ C, int ldc, float alpha,
             const float* __restrict__ biasN, const float* __restrict__ biasN2,
             const float* __restrict__ biasM,
             bf16* __restrict__ Chi, bf16* __restrict__ Clo)
{
    __shared__ float As[2][8][128];
    __shared__ float Bs[2][8][128];
    const int tid = threadIdx.x;
    const int m0 = blockIdx.y * 128, n0 = blockIdx.x * 128;
    const int lrow = tid >> 1, lk = (tid & 1) * 4;
    const int ty = tid >> 4, tx = tid & 15;

    float acc[8][8];
#pragma unroll
    for (int i = 0; i < 8; ++i)
#pragma unroll
        for (int j = 0; j < 8; ++j) acc[i][j] = 0.f;

    const int nk1 = K1 >> 3;
    const int nk2 = A2 ? (K2 >> 3) : 0;
    const int nkt = nk1 + nk2;

    float4 ra, rb;
    auto load_t = [&](int t) {
        if (t < nk1) {
            ra = *reinterpret_cast<const float4*>(A + (size_t)(m0 + lrow) * K1 + (t << 3) + lk);
            rb = *reinterpret_cast<const float4*>(B + (size_t)(n0 + lrow) * K1 + (t << 3) + lk);
        } else {
            int u = t - nk1;
            ra = *reinterpret_cast<const float4*>(A2 + (size_t)(m0 + lrow) * K2 + (u << 3) + lk);
            rb = *reinterpret_cast<const float4*>(B2 + (size_t)(n0 + lrow) * K2 + (u << 3) + lk);
        }
    };

    load_t(0);
    As[0][lk+0][lrow]=ra.x; As[0][lk+1][lrow]=ra.y; As[0][lk+2][lrow]=ra.z; As[0][lk+3][lrow]=ra.w;
    Bs[0][lk+0][lrow]=rb.x; Bs[0][lk+1][lrow]=rb.y; Bs[0][lk+2][lrow]=rb.z; Bs[0][lk+3][lrow]=rb.w;
    __syncthreads();

    int cur = 0;
    for (int t = 0; t < nkt; ++t) {
        const bool more = (t + 1 < nkt);
        if (more) load_t(t + 1);
        const float(*Asc)[128] = As[cur];
        const float(*Bsc)[128] = Bs[cur];
#pragma unroll
        for (int kk = 0; kk < 8; ++kk) {
            float4 a0 = *reinterpret_cast<const float4*>(&Asc[kk][ty << 2]);
            float4 a1 = *reinterpret_cast<const float4*>(&Asc[kk][(ty << 2) + 64]);
            float4 b0 = *reinterpret_cast<const float4*>(&Bsc[kk][tx << 2]);
            float4 b1 = *reinterpret_cast<const float4*>(&Bsc[kk][(tx << 2) + 64]);
            float av[8] = {a0.x,a0.y,a0.z,a0.w,a1.x,a1.y,a1.z,a1.w};
            float bv[8] = {b0.x,b0.y,b0.z,b0.w,b1.x,b1.y,b1.z,b1.w};
#pragma unroll
            for (int i = 0; i < 8; ++i)
#pragma unroll
                for (int j = 0; j < 8; ++j) acc[i][j] += av[i] * bv[j];
        }
        if (more) {
            int nxt = cur ^ 1;
            As[nxt][lk+0][lrow]=ra.x; As[nxt][lk+1][lrow]=ra.y; As[nxt][lk+2][lrow]=ra.z; As[nxt][lk+3][lrow]=ra.w;
            Bs[nxt][lk+0][lrow]=rb.x; Bs[nxt][lk+1][lrow]=rb.y; Bs[nxt][lk+2][lrow]=rb.z; Bs[nxt][lk+3][lrow]=rb.w;
            __syncthreads();
            cur = nxt;
        }
    }
#pragma unroll
    for (int ii = 0; ii < 2; ++ii)
#pragma unroll
        for (int i = 0; i < 4; ++i) {
            int row = m0 + ii * 64 + (ty << 2) + i;
            float bm = biasM ? biasM[row] : 0.f;
#pragma unroll
            for (int jj = 0; jj < 2; ++jj)
#pragma unroll
                for (int j = 0; j < 4; ++j) {
                    int col = n0 + jj * 64 + (tx << 2) + j;
                    float v = alpha * acc[ii * 4 + i][jj * 4 + j] + bm;
                    if (biasN)  v += biasN[col];
                    if (biasN2) v += biasN2[col];
                    C[(size_t)row * ldc + col] = v;
                    if (Chi) {
                        bf16 h = __float2bfloat16(v);
                        Chi[(size_t)row * ldc + col] = h;
                        Clo[(size_t)row * ldc + col] = __float2bfloat16(v - __bfloat162float(h));
                    }
                }
        }
}

// ---------------------------------------------------------------------------
// fp32 SIMT NN GEMM (512x512x512): C = A·Bz, bf16 hi/lo pair out.
// blockIdx.z picks (B1sel, C1) vs (B2sel, C2).
// ---------------------------------------------------------------------------
__global__ __launch_bounds__(256, 2)
void gemm_nn_pair2(const float* __restrict__ A,
                   const float* __restrict__ Ba, const float* __restrict__ Bb,
                   bf16* __restrict__ C1h, bf16* __restrict__ C1l,
                   bf16* __restrict__ C2h, bf16* __restrict__ C2l)
{
    const float* B = blockIdx.z ? Bb : Ba;
    bf16* Chi = blockIdx.z ? C2h : C1h;
    bf16* Clo = blockIdx.z ? C2l : C1l;

    __shared__ float As[2][8][128];
    __shared__ float Bs[2][8][128];
    const int tid = threadIdx.x;
    const int m0 = blockIdx.y * 128, n0 = blockIdx.x * 128;
    const int lrow = tid >> 1, lk = (tid & 1) * 4;
    const int bk = tid >> 5, bc = (tid & 31) * 4;
    const int ty = tid >> 4, tx = tid & 15;

    float acc[8][8];
#pragma unroll
    for (int i = 0; i < 8; ++i)
#pragma unroll
        for (int j = 0; j < 8; ++j) acc[i][j] = 0.f;

    const int nkt = DIM / 8;

    float4 ra, rb;
    auto load_t = [&](int t) {
        int kb = t << 3;
        ra = *reinterpret_cast<const float4*>(A + (size_t)(m0 + lrow) * DIM + kb + lk);
        rb = *reinterpret_cast<const float4*>(B + (size_t)(kb + bk) * DIM + n0 + bc);
    };

    load_t(0);
    As[0][lk+0][lrow]=ra.x; As[0][lk+1][lrow]=ra.y; As[0][lk+2][lrow]=ra.z; As[0][lk+3][lrow]=ra.w;
    *reinterpret_cast<float4*>(&Bs[0][bk][bc]) = rb;
    __syncthreads();

    int cur = 0;
    for (int t = 0; t < nkt; ++t) {
        const bool more = (t + 1 < nkt);
        if (more) load_t(t + 1);
        const float(*Asc)[128] = As[cur];
        const float(*Bsc)[128] = Bs[cur];
#pragma unroll
        for (int kk = 0; kk < 8; ++kk) {
            float4 a0 = *reinterpret_cast<const float4*>(&Asc[kk][ty << 2]);
            float4 a1 = *reinterpret_cast<const float4*>(&Asc[kk][(ty << 2) + 64]);
            float4 b0 = *reinterpret_cast<const float4*>(&Bsc[kk][tx << 2]);
            float4 b1 = *reinterpret_cast<const float4*>(&Bsc[kk][(tx << 2) + 64]);
            float av[8] = {a0.x,a0.y,a0.z,a0.w,a1.x,a1.y,a1.z,a1.w};
            float bv[8] = {b0.x,b0.y,b0.z,b0.w,b1.x,b1.y,b1.z,b1.w};
#pragma unroll
            for (int i = 0; i < 8; ++i)
#pragma unroll
                for (int j = 0; j < 8; ++j) acc[i][j] += av[i] * bv[j];
        }
        if (more) {
            int nxt = cur ^ 1;
            As[nxt][lk+0][lrow]=ra.x; As[nxt][lk+1][lrow]=ra.y; As[nxt][lk+2][lrow]=ra.z; As[nxt][lk+3][lrow]=ra.w;
            *reinterpret_cast<float4*>(&Bs[nxt][bk][bc]) = rb;
            __syncthreads();
            cur = nxt;
        }
    }
#pragma unroll
    for (int ii = 0; ii < 2; ++ii)
#pragma unroll
        for (int i = 0; i < 4; ++i) {
            int row = m0 + ii * 64 + (ty << 2) + i;
#pragma unroll
            for (int jj = 0; jj < 2; ++jj)
#pragma unroll
                for (int j = 0; j < 4; ++j) {
                    int col = n0 + jj * 64 + (tx << 2) + j;
                    float v = acc[ii * 4 + i][jj * 4 + j];
                    bf16 h = __float2bfloat16(v);
                    Chi[(size_t)row * DIM + col] = h;
                    Clo[(size_t)row * DIM + col] = __float2bfloat16(v - __bfloat162float(h));
                }
        }
}

// biasK[m] = SCALE * sum_d (bq[d]+bgp[d]) * Km[m,d]   (warp per row)
__global__ void biask_kernel(const float* __restrict__ Km, const float* __restrict__ bq,
                             const float* __restrict__ bgp, float* __restrict__ biasK)
{
    const int warp = threadIdx.x >> 5;
    const int lane = threadIdx.x & 31;
    const int row = blockIdx.x * 8 + warp;
    float s = 0.f;
#pragma unroll
    for (int j = 0; j < 16; ++j) {
        int d = lane + 32 * j;
        s += (bq[d] + bgp[d]) * Km[row * DIM + d];
    }
#pragma unroll
    for (int o = 16; o; o >>= 1) s += __shfl_xor_sync(0xffffffffu, s, o);
    if (lane == 0) biasK[row] = ATT_SCALE * s;
}

// kp[m,d] = (sum_z parts[z][m,d]) / sums1[m]   (deferred pool normalization)
__global__ void reduce_parts(const float* __restrict__ parts, const float* __restrict__ sums1,
                             float* __restrict__ kp)
{
    int i = blockIdx.x * 256 + threadIdx.x;
    float s = 0.f;
#pragma unroll
    for (int z = 0; z < ZSL; ++z)
        s += parts[(size_t)z * (MTOK * DIM) + i];
    kp[i] = s / sums1[i >> 9];   // DIM = 512
}

__global__ void convert_pair(const float* __restrict__ x, bf16* __restrict__ h,
                             bf16* __restrict__ l, int n)
{
    int i = (blockIdx.x * 256 + threadIdx.x) * 4;
    if (i >= n) return;
    float4 v = *reinterpret_cast<const float4*>(x + i);
    bf16 h0 = __float2bfloat16(v.x), h1 = __float2bfloat16(v.y);
    bf16 h2 = __float2bfloat16(v.z), h3 = __float2bfloat16(v.w);
    __nv_bfloat162 a, b; a.x = h0; a.y = h1; b.x = h2; b.y = h3;
    reinterpret_cast<__nv_bfloat162*>(h + i)[0] = a;
    reinterpret_cast<__nv_bfloat162*>(h + i)[1] = b;
    __nv_bfloat162 c, d;
    c.x = __float2bfloat16(v.x - __bfloat162float(h0));
    c.y = __float2bfloat16(v.y - __bfloat162float(h1));
    d.x = __float2bfloat16(v.z - __bfloat162float(h2));
    d.y = __float2bfloat16(v.w - __bfloat162float(h3));
    reinterpret_cast<__nv_bfloat162*>(l + i)[0] = c;
    reinterpret_cast<__nv_bfloat162*>(l + i)[1] = d;
}

// out = LayerNorm(OP/sum + g) * gamma + beta (warp per row)
__global__ void add_ln(const float* __restrict__ OP, const float* __restrict__ G,
                       const float* __restrict__ sums,
                       const float* __restrict__ gamma, const float* __restrict__ beta,
                       float* __restrict__ out)
{
    const int warp = threadIdx.x >> 5;
    const int lane = threadIdx.x & 31;
    const size_t row = (size_t)blockIdx.x * 8 + warp;
    const float4* po = reinterpret_cast<const float4*>(OP + row * DIM);
    const float4* pg = reinterpret_cast<const float4*>(G + row * DIM);
    float4* pw = reinterpret_cast<float4*>(out + row * DIM);
    const float inv = 1.0f / sums[row];

    float4 x[4];
    float s1 = 0.f, s2 = 0.f;
#pragma unroll
    for (int j = 0; j < 4; ++j) {
        float4 a = po[lane + 32 * j];
        float4 b = pg[lane + 32 * j];
        a.x = a.x * inv + b.x; a.y = a.y * inv + b.y;
        a.z = a.z * inv + b.z; a.w = a.w * inv + b.w;
        x[j] = a;
        s1 += (a.x + a.y) + (a.z + a.w);
        s2 += (a.x * a.x + a.y * a.y) + (a.z * a.z + a.w * a.w);
    }
#pragma unroll
    for (int o = 16; o; o >>= 1) {
        s1 += __shfl_xor_sync(0xffffffffu, s1, o);
        s2 += __shfl_xor_sync(0xffffffffu, s2, o);
    }
    const float mu = s1 * (1.0f / DIM);
    const float var = s2 * (1.0f / DIM) - mu * mu;
    const float rs = rsqrtf(var + 1e-5f);
    const float4* pgm = reinterpret_cast<const float4*>(gamma);
    const float4* pbt = reinterpret_cast<const float4*>(beta);
#pragma unroll
    for (int j = 0; j < 4; ++j) {
        float4 gm = pgm[lane + 32 * j];
        float4 bt = pbt[lane + 32 * j];
        float4 o4;
        o4.x = (x[j].x - mu) * rs * gm.x + bt.x;
        o4.y = (x[j].y - mu) * rs * gm.y + bt.y;
        o4.z = (x[j].z - mu) * rs * gm.z + bt.z;
        o4.w = (x[j].w - mu) * rs * gm.w + bt.w;
        pw[lane + 32 * j] = o4;
    }
}

// ---------------------------------------------------------------------------
extern "C" void kernel_launch(void* const* d_in, const int* in_sizes, int n_in,
                              void* d_out, int out_size)
{
    const float* g   = (const float*)d_in[0];
    const float* g_p = (const float*)d_in[1];
    const float* W   = (const float*)d_in[2];
    const float* Wq  = (const float*)d_in[3];
    const float* bq  = (const float*)d_in[4];
    const float* Wk  = (const float*)d_in[5];
    const float* bk  = (const float*)d_in[6];
    const float* Wv  = (const float*)d_in[7];
    const float* bv  = (const float*)d_in[8];
    const float* Wgp = (const float*)d_in[9];
    const float* bgp = (const float*)d_in[10];
    const float* Wkp = (const float*)d_in[11];
    const float* bkp = (const float*)d_in[12];
    const float* gam = (const float*)d_in[13];
    const float* bet = (const float*)d_in[14];
    float* out = (float*)d_out;

    float *OP, *parts, *kp, *Km, *Vt, *sums, *sums1, *biasK;
    bf16 *gh,*gl,*gph,*gpl,*Ph,*Pl;
    bf16 *Wsh,*Wsl,*B1h,*B1l,*B2h,*B2l,*Vth,*Vtl;
    cudaGetSymbolAddress((void**)&OP, d_OP);
    cudaGetSymbolAddress((void**)&parts, d_parts); cudaGetSymbolAddress((void**)&kp, d_kp);
    cudaGetSymbolAddress((void**)&Km, d_Km);     cudaGetSymbolAddress((void**)&Vt, d_Vt);
    cudaGetSymbolAddress((void**)&sums, d_sums); cudaGetSymbolAddress((void**)&sums1, d_sums1);
    cudaGetSymbolAddress((void**)&biasK, d_biasK);
    cudaGetSymbolAddress((void**)&gh, d_gh);     cudaGetSymbolAddress((void**)&gl, d_gl);
    cudaGetSymbolAddress((void**)&gph, d_gph);   cudaGetSymbolAddress((void**)&gpl, d_gpl);
    cudaGetSymbolAddress((void**)&Ph, d_Ph);     cudaGetSymbolAddress((void**)&Pl, d_Pl);
    cudaGetSymbolAddress((void**)&Wsh, d_Wsh);   cudaGetSymbolAddress((void**)&Wsl, d_Wsl);
    cudaGetSymbolAddress((void**)&B1h, d_B1h);   cudaGetSymbolAddress((void**)&B1l, d_B1l);
    cudaGetSymbolAddress((void**)&B2h, d_B2h);   cudaGetSymbolAddress((void**)&B2l, d_B2l);
    cudaGetSymbolAddress((void**)&Vth, d_Vth);   cudaGetSymbolAddress((void**)&Vtl, d_Vtl);

    cudaFuncSetAttribute(gemm3<0>, cudaFuncAttributeMaxDynamicSharedMemorySize, GEMM_SMEM);
    cudaFuncSetAttribute(gemm3<1>, cudaFuncAttributeMaxDynamicSharedMemorySize, GEMM_SMEM);

    const int NGD = NG * DIM;
    // aux (no transpose needed: kp GEMM consumes gph/gpl k-major)
    cudaMemsetAsync(sums, 0, NG * sizeof(float));
    cudaMemsetAsync(sums1, 0, MTOK * sizeof(float));
    convert_pair<<<NGD / 1024, 256>>>(g, gh, gl, NGD);
    convert_pair<<<NGD / 1024, 256>>>(g_p, gph, gpl, NGD);
    convert_pair<<<(MTOK * DIM) / 1024, 256>>>(W, Wsh, Wsl, MTOK * DIM);

    // expS1 = exp(Ws·g^T - 100) -> bf16 pair + atomic row sums (sums1).
    gemm3<0><<<dim3(MTOK / 128, NG / 128, 1), 256, GEMM_SMEM>>>(
        Wsh, Wsl, gh, gl, DIM, nullptr, nullptr, nullptr, nullptr, 0,
        nullptr, NG, 1.0f, nullptr, Ph, Pl, 1, POOL_SHIFT, sums1, 1, 0, DIM, 0);
    // kp_un = expS1 · g_p  (NN mode: B = gph/gpl k-major, ldbT = DIM;
    // split-K over 16 slices -> 256 blocks = 1 clean wave)
    gemm3<1><<<dim3(DIM / 128, MTOK / 128, ZSL), 256, GEMM_SMEM>>>(
        Ph, Pl, gph, gpl, NG, nullptr, nullptr, nullptr, nullptr, 0,
        parts, DIM, 1.0f, nullptr, nullptr, nullptr, 0, 0.f, nullptr, 0, DIM,
        KSL, (size_t)MTOK * DIM);
    // kp = (sum parts) / sums1   (deferred pool normalization)
    reduce_parts<<<(MTOK * DIM) / 256, 256>>>(parts, sums1, kp);
    // K = Ws·Wk^T + kp·Wkp^T + bk + bkp   (small, fp32)
    gemm_nt<<<dim3(4, 4), 256>>>(W, Wk, DIM, kp, Wkp, DIM, Km, DIM, 1.0f, bk, bkp, nullptr,
                                 nullptr, nullptr);
    // Vt[d,m] = (Wv·Ws^T)[d,m] + bv[d]  -> fp32 + bf16 pair fused
    gemm_nt<<<dim3(4, 4), 256>>>(Wv, W, DIM, nullptr, nullptr, 0, Vt, MTOK, 1.0f,
                                 nullptr, nullptr, bv, Vth, Vtl);
    // B1 = K·Wq, B2 = K·Wgp (bf16 pair, one launch); biasK = SCALE*(bq+bgp)·K^T
    gemm_nn_pair2<<<dim3(4, 4, 2), 256>>>(Km, Wq, Wgp, B1h, B1l, B2h, B2l);
    biask_kernel<<<MTOK / 8, 256>>>(Km, bq, bgp, biasK);
    // expS2 = exp(SCALE*(g·B1^T + gp·B2^T) + biasK) -> bf16 pair + row sums
    gemm3<0><<<dim3(MTOK / 128, NG / 128, 1), 256, GEMM_SMEM>>>(
        gh, gl, B1h, B1l, DIM, gph, gpl, B2h, B2l, DIM,
        nullptr, MTOK, ATT_SCALE, biasK, Ph, Pl, 1, 0.f, sums, 0, 0, DIM, 0);
    // OP = expS2 · V (unnormalized; NT with Vt)
    gemm3<0><<<dim3(DIM / 128, NG / 128, 1), 256, GEMM_SMEM>>>(
        Ph, Pl, Vth, Vtl, MTOK, nullptr, nullptr, nullptr, nullptr, 0,
        OP, DIM, 1.0f, nullptr, nullptr, nullptr, 0, 0.f, nullptr, 0, 0, MTOK, 0);
    // out = LN(OP/sum + g)
    add_ln<<<NG / 8, 256>>>(OP, g, sums, gam, bet, out);
}